// round 9
// baseline (speedup 1.0000x reference)
#include <cuda_runtime.h>
#include <cstdint>

#define D 12
#define KCB 512
#define THREADS 256
#define TPB 256
#define G_WIN 2.5e-5f

typedef unsigned long long u64;

__device__ float        g_partial[2048];
__device__ unsigned int g_ctr = 0;

__device__ __forceinline__ uint32_t f2tf32(float f) {
    uint32_t r; asm("cvt.rna.tf32.f32 %0, %1;" : "=r"(r) : "f"(f)); return r;
}
__device__ __forceinline__ void mma8(float* c, const uint32_t* a, const uint32_t* b) {
    asm volatile("mma.sync.aligned.m16n8k8.row.col.f32.tf32.tf32.f32 "
        "{%0,%1,%2,%3}, {%4,%5,%6,%7}, {%8,%9}, {%0,%1,%2,%3};"
        : "+f"(c[0]), "+f"(c[1]), "+f"(c[2]), "+f"(c[3])
        : "r"(a[0]), "r"(a[1]), "r"(a[2]), "r"(a[3]), "r"(b[0]), "r"(b[1]));
}

// ---- shared layout in 32-bit words ----
#define BSTR    520                      // B row stride (words): bank = (8k+n)%32, conflict-free
#define OFF_BH  0                        // 16*520
#define OFF_BL  (OFF_BH + 16 * BSTR)     // 16*520
#define OFF_AH  (OFF_BL + 16 * BSTR)     // 256*16
#define OFF_AL  (OFF_AH + TPB * 16)      // 256*16
#define OFF_W2  (OFF_AL + TPB * 16)      // 512
#define OFF_RES (OFF_W2 + KCB)           // 256
#define OFF_RED (OFF_RES + TPB)          // 256
#define OFF_AMB (OFF_RED + TPB)          // 256
#define OFF_KEY (OFF_AMB + TPB)          // 512 (u64[256])
#define OFF_MISC (OFF_KEY + 512)         // 32
#define SMEM_WORDS (OFF_MISC + 32)
#define SMEM_DYN (SMEM_WORDS * 4)

__global__ void __launch_bounds__(THREADS, 2)
vq_hmma_kernel(const float* __restrict__ x, const float* __restrict__ cb,
               int tokens, int K,
               float* __restrict__ q_out, float* __restrict__ idx_out,
               float* __restrict__ loss_out)
{
    extern __shared__ uint32_t sm[];
    uint32_t* sBh  = sm + OFF_BH;
    uint32_t* sBl  = sm + OFF_BL;
    uint32_t* sAh  = sm + OFF_AH;
    uint32_t* sAl  = sm + OFF_AL;
    float*    s_w2 = (float*)(sm + OFF_W2);
    uint32_t* s_res = sm + OFF_RES;
    float*    s_red = (float*)(sm + OFF_RED);
    int*      s_amb = (int*)(sm + OFF_AMB);
    u64*      s_key = (u64*)(sm + OFF_KEY);
    int*      s_ambN  = (int*)(sm + OFF_MISC);
    int*      s_last  = (int*)(sm + OFF_MISC + 1);
    float*    s_xa    = (float*)(sm + OFF_MISC + 2);   // 13 floats

    const int tid = threadIdx.x;
    const int token = blockIdx.x * TPB + tid;
    const bool tok_ok = (token < tokens);
    if (tid == 0) *s_ambN = 0;

    // ---- stage A: this thread's token, tf32 hi/lo, row = tid ----
    {
        float4 a = {0,0,0,0}, b = {0,0,0,0}, c = {0,0,0,0};
        if (tok_ok) { const float4* p = (const float4*)(x + (size_t)token * D); a=p[0]; b=p[1]; c=p[2]; }
        const float xv[D] = {a.x,a.y,a.z,a.w, b.x,b.y,b.z,b.w, c.x,c.y,c.z,c.w};
        #pragma unroll
        for (int d = 0; d < D; d++) {
            const uint32_t hi = f2tf32(xv[d]);
            sAh[tid * 16 + d] = hi;
            sAl[tid * 16 + d] = f2tf32(xv[d] - __uint_as_float(hi));
        }
        sAh[tid * 16 + 12] = f2tf32(1.0f);
        sAl[tid * 16 + 12] = 0;
        #pragma unroll
        for (int d = 13; d < 16; d++) { sAh[tid * 16 + d] = 0; sAl[tid * 16 + d] = 0; }
    }

    // ---- stage B: codes k = tid, tid+256; [k-major rows, stride 520] ----
    #pragma unroll
    for (int s = 0; s < 2; s++) {
        const int k = tid + s * THREADS;
        if (k < KCB) {
            float wv[D];
            float w2 = 0.f;
            if (k < K) {
                const float4* wp = (const float4*)(cb + (size_t)k * D);
                const float4 a = wp[0], b = wp[1], c = wp[2];
                wv[0]=a.x; wv[1]=a.y; wv[2]=a.z; wv[3]=a.w;
                wv[4]=b.x; wv[5]=b.y; wv[6]=b.z; wv[7]=b.w;
                wv[8]=c.x; wv[9]=c.y; wv[10]=c.z; wv[11]=c.w;
                #pragma unroll
                for (int d = 0; d < D; d++) w2 = fmaf(wv[d], wv[d], w2);
            } else {
                #pragma unroll
                for (int d = 0; d < D; d++) wv[d] = 0.f;
            }
            s_w2[k] = w2;
            #pragma unroll
            for (int d = 0; d < D; d++) {
                const uint32_t hi = f2tf32(wv[d]);
                sBh[d * BSTR + k] = hi;
                sBl[d * BSTR + k] = f2tf32(wv[d] - __uint_as_float(hi));
            }
            const float bias = (k < K) ? (-0.5f * w2) : -1.0e30f;
            const uint32_t bh = f2tf32(bias);
            sBh[12 * BSTR + k] = bh;
            sBl[12 * BSTR + k] = (k < K) ? f2tf32(bias - __uint_as_float(bh)) : 0;
            #pragma unroll
            for (int d = 13; d < 16; d++) { sBh[d * BSTR + k] = 0; sBl[d * BSTR + k] = 0; }
        }
    }
    __syncthreads();

    // ---- warp-level MMA: warp w owns tokens [w*32, w*32+32) of this block ----
    const int lane = tid & 31, wrp = tid >> 5;
    const int gid = lane >> 2, tig = lane & 3;

    uint32_t Ah[2][2][4], Al[2][2][4];
    #pragma unroll
    for (int mt = 0; mt < 2; mt++) {
        const int rb = wrp * 32 + mt * 16;
        #pragma unroll
        for (int s = 0; s < 2; s++) {
            const int kc = 8 * s + tig;
            Ah[mt][s][0] = sAh[(rb + gid)     * 16 + kc];
            Ah[mt][s][1] = sAh[(rb + gid + 8) * 16 + kc];
            Ah[mt][s][2] = sAh[(rb + gid)     * 16 + kc + 4];
            Ah[mt][s][3] = sAh[(rb + gid + 8) * 16 + kc + 4];
            Al[mt][s][0] = sAl[(rb + gid)     * 16 + kc];
            Al[mt][s][1] = sAl[(rb + gid + 8) * 16 + kc];
            Al[mt][s][2] = sAl[(rb + gid)     * 16 + kc + 4];
            Al[mt][s][3] = sAl[(rb + gid + 8) * 16 + kc + 4];
        }
    }

    float m1[4], m2[4];
    int   i1[4];
    #pragma unroll
    for (int r = 0; r < 4; r++) { m1[r] = -3.4e38f; m2[r] = -3.4e38f; i1[r] = 0; }

    #pragma unroll 1
    for (int it = 0; it < KCB / 8; it++) {
        const int col = it * 8 + gid;
        uint32_t bh[2][2], bl[2][2];
        bh[0][0] = sBh[tig * BSTR + col];        bh[0][1] = sBh[(tig + 4) * BSTR + col];
        bh[1][0] = sBh[(8 + tig) * BSTR + col];  bh[1][1] = sBh[(12 + tig) * BSTR + col];
        bl[0][0] = sBl[tig * BSTR + col];        bl[0][1] = sBl[(tig + 4) * BSTR + col];
        bl[1][0] = sBl[(8 + tig) * BSTR + col];  bl[1][1] = sBl[(12 + tig) * BSTR + col];

        float ahh[2][4] = {}, ahl[2][4] = {}, alh[2][4] = {};
        #pragma unroll
        for (int mt = 0; mt < 2; mt++) {
            #pragma unroll
            for (int s = 0; s < 2; s++) mma8(ahh[mt], Ah[mt][s], bh[s]);
            #pragma unroll
            for (int s = 0; s < 2; s++) mma8(ahl[mt], Ah[mt][s], bl[s]);
            #pragma unroll
            for (int s = 0; s < 2; s++) mma8(alh[mt], Al[mt][s], bh[s]);
        }
        #pragma unroll
        for (int mt = 0; mt < 2; mt++) {
            #pragma unroll
            for (int e = 0; e < 4; e++) {
                const float S = (ahh[mt][e] + ahl[mt][e]) + alh[mt][e];
                const int r = mt * 2 + (e >> 1);
                const int kidx = it * 8 + 2 * tig + (e & 1);
                m2[r] = fmaxf(m2[r], fminf(S, m1[r]));
                i1[r] = (S > m1[r]) ? kidx : i1[r];
                m1[r] = fmaxf(m1[r], S);
            }
        }
    }

    // ---- merge top-2 across the 4 tig lanes sharing each row ----
    #pragma unroll
    for (int off = 1; off <= 2; off <<= 1) {
        #pragma unroll
        for (int r = 0; r < 4; r++) {
            const float om1 = __shfl_xor_sync(0xFFFFFFFFu, m1[r], off);
            const float om2 = __shfl_xor_sync(0xFFFFFFFFu, m2[r], off);
            const int   oi1 = __shfl_xor_sync(0xFFFFFFFFu, i1[r], off);
            const float nm2 = fmaxf(fmaxf(m2[r], om2), fminf(m1[r], om1));
            const bool take = (om1 > m1[r]) || (om1 == m1[r] && oi1 < i1[r]);
            i1[r] = take ? oi1 : i1[r];
            m1[r] = fmaxf(m1[r], om1);
            m2[r] = nm2;
        }
    }
    if (tig == 0) {
        #pragma unroll
        for (int r = 0; r < 4; r++) {
            const int row = wrp * 32 + (r >> 1) * 16 + gid + (r & 1) * 8;
            const bool amb = !((m1[r] - m2[r]) > G_WIN);
            s_res[row] = (uint32_t)i1[r] | (amb ? 0x80000000u : 0u);
        }
    }
    __syncthreads();

    // ---- per-token epilogue state ----
    const uint32_t res = s_res[tid];
    int best_i = (int)(res & 0x7FFFFFFFu);
    const bool amb = (res >> 31) != 0;

    // reload exact x (L2-hot)
    float xv[D];
    {
        float4 a = {0,0,0,0}, b = {0,0,0,0}, c = {0,0,0,0};
        if (tok_ok) { const float4* p = (const float4*)(x + (size_t)token * D); a=p[0]; b=p[1]; c=p[2]; }
        xv[0]=a.x; xv[1]=a.y; xv[2]=a.z; xv[3]=a.w;
        xv[4]=b.x; xv[5]=b.y; xv[6]=b.z; xv[7]=b.w;
        xv[8]=c.x; xv[9]=c.y; xv[10]=c.z; xv[11]=c.w;
    }
    float x2 = 0.f;
    #pragma unroll
    for (int d = 0; d < D; d++) x2 = fmaf(xv[d], xv[d], x2);

    if (tok_ok && amb) {
        const int pos = atomicAdd(s_ambN, 1);
        s_amb[pos] = tid;
    }
    __syncthreads();

    // ---- exact in-block fallback (bit-faithful fp32 chain), ~0.5 tokens/block ----
    const int nA = *s_ambN;
    for (int a = 0; a < nA; a++) {
        const int atid = s_amb[a];
        if (tid == atid) {
            #pragma unroll
            for (int d = 0; d < D; d++) s_xa[d] = xv[d];
            s_xa[12] = x2;
        }
        __syncthreads();
        float ax[D];
        const float ax2 = s_xa[12];
        #pragma unroll
        for (int d = 0; d < D; d++) ax[d] = s_xa[d];
        u64 key = ~0ull;
        #pragma unroll
        for (int rI = 0; rI < 2; rI++) {
            const int k = tid * 2 + rI;
            if (k < K) {
                const float4* wp = (const float4*)(cb + (size_t)k * D);
                const float4 aa = wp[0], bb = wp[1], cc = wp[2];
                const float wv[D] = {aa.x,aa.y,aa.z,aa.w, bb.x,bb.y,bb.z,bb.w, cc.x,cc.y,cc.z,cc.w};
                float xw = ax[0] * wv[0];
                #pragma unroll
                for (int d = 1; d < D; d++) xw = fmaf(ax[d], wv[d], xw);
                const float u = fmaf(xw, -2.0f, ax2);   // fl(x2 - 2*xw)
                const float dist = u + s_w2[k];         // fl(u + w2)
                const u64 kk = ((u64)__float_as_uint(dist) << 32) | (uint32_t)k;
                key = (kk < key) ? kk : key;
            }
        }
        s_key[tid] = key;
        __syncthreads();
        #pragma unroll
        for (int s = THREADS / 2; s > 0; s >>= 1) {
            if (tid < s) { const u64 o = s_key[tid + s]; if (o < s_key[tid]) s_key[tid] = o; }
            __syncthreads();
        }
        if (tid == atid) best_i = (int)(uint32_t)(s_key[0] & 0xFFFFFFFFu);
        __syncthreads();
    }

    // ---- outputs: qst = fl(x + fl(q - x)), indices, loss ----
    float lsum = 0.f;
    if (tok_ok) {
        const float4* wp = (const float4*)(cb + (size_t)best_i * D);
        const float4 aa = wp[0], bb = wp[1], cc = wp[2];
        const float qv[D] = {aa.x,aa.y,aa.z,aa.w, bb.x,bb.y,bb.z,bb.w, cc.x,cc.y,cc.z,cc.w};
        float qst[D];
        #pragma unroll
        for (int d = 0; d < D; d++) {
            const float d1 = qv[d] - xv[d];
            qst[d] = xv[d] + d1;
            lsum = fmaf(d1, d1, lsum);
        }
        if (q_out) {
            float4* o = (float4*)(q_out + (size_t)token * D);
            o[0] = make_float4(qst[0], qst[1], qst[2],  qst[3]);
            o[1] = make_float4(qst[4], qst[5], qst[6],  qst[7]);
            o[2] = make_float4(qst[8], qst[9], qst[10], qst[11]);
        }
        if (idx_out) idx_out[token] = (float)best_i;
    }

    if (loss_out) {
        s_red[tid] = lsum;
        __syncthreads();
        #pragma unroll
        for (int s = THREADS / 2; s > 0; s >>= 1) {
            if (tid < s) s_red[tid] += s_red[tid + s];
            __syncthreads();
        }
        if (tid == 0) {
            g_partial[blockIdx.x] = s_red[0];
            __threadfence();
            const unsigned old = atomicInc(&g_ctr, gridDim.x - 1);  // self-resets
            *s_last = (old == gridDim.x - 1);
        }
        __syncthreads();
        if (*s_last) {
            __threadfence();
            float v = 0.f;
            for (int i = tid; i < (int)gridDim.x; i += THREADS) v += g_partial[i];
            s_red[tid] = v;
            __syncthreads();
            #pragma unroll
            for (int s = THREADS / 2; s > 0; s >>= 1) {
                if (tid < s) s_red[tid] += s_red[tid + s];
                __syncthreads();
            }
            if (tid == 0) {
                const float m = s_red[0] / ((float)tokens * 12.0f);
                loss_out[0] = m + 0.25f * m;
            }
        }
    }
}

extern "C" void kernel_launch(void* const* d_in, const int* in_sizes, int n_in,
                              void* d_out, int out_size)
{
    const float* x;
    const float* cb;
    int xs, cs;
    if (in_sizes[0] >= in_sizes[1]) {
        x = (const float*)d_in[0]; cb = (const float*)d_in[1];
        xs = in_sizes[0]; cs = in_sizes[1];
    } else {
        x = (const float*)d_in[1]; cb = (const float*)d_in[0];
        xs = in_sizes[1]; cs = in_sizes[0];
    }
    const int tokens = xs / D;
    int K = cs / D;
    if (K > KCB) K = KCB;

    float* out = (float*)d_out;
    const long long QN = (long long)tokens * D;

    float* q_out    = nullptr;
    float* idx_out  = nullptr;
    float* loss_out = nullptr;
    if ((long long)out_size == (long long)tokens) {
        idx_out = out;
    } else {
        q_out = out;
        if ((long long)out_size >= QN + tokens)     idx_out  = out + QN;
        if ((long long)out_size >= QN + tokens + 1) loss_out = out + QN + tokens;
        else if ((long long)out_size == QN + 1)     loss_out = out + QN;
    }

    static bool attr_set = false;
    if (!attr_set) {
        cudaFuncSetAttribute(vq_hmma_kernel,
                             cudaFuncAttributeMaxDynamicSharedMemorySize, SMEM_DYN);
        attr_set = true;
    }

    int grid = (tokens + TPB - 1) / TPB;   // 512 for this shape
    if (grid > 2048) grid = 2048;          // g_partial capacity (not hit)

    vq_hmma_kernel<<<grid, THREADS, SMEM_DYN>>>(x, cb, tokens, K, q_out, idx_out, loss_out);
}

// round 10
// speedup vs baseline: 1.7561x; 1.7561x over previous
#include <cuda_runtime.h>
#include <cuda_fp16.h>
#include <cstdint>

#define D 12
#define KCB 512
#define THREADS 128
#define TPB 128

typedef unsigned long long u64;

__device__ float        g_partial[2048];
__device__ unsigned int g_ctr = 0;

// ---- shared layout (32-bit words) ----
#define BSTR   520                      // B plane row stride: 520 % 32 == 8 -> conflict-free frags
#define BPL    2080                     // plane size (4*520)
#define OFF_B  0                        // 2 planes = 4160 words
#define OFF_A  4160                     // 128 tokens * ASTR
#define ASTR   12
#define OFF_W2  (OFF_A + TPB * ASTR)    // 512 words
#define OFF_GW  (OFF_W2 + KCB)          // 128
#define OFF_RES (OFF_GW + TPB)          // 128
#define OFF_RED (OFF_RES + TPB)         // 128
#define OFF_AMB (OFF_RED + TPB)         // 128
#define OFF_MISC (OFF_AMB + TPB)        // 8: [0]=ambN, [1]=last, [2]=wmax bits
#define SMEM_WORDS (OFF_MISC + 8)
#define SMEM_DYN (SMEM_WORDS * 4)       // ~26.9 KB -> 7 blocks/SM

__device__ __forceinline__ uint32_t pack_h2(float a, float b) {
    __half2 h = __halves2half2(__float2half_rn(a), __float2half_rn(b));
    return *reinterpret_cast<uint32_t*>(&h);
}
__device__ __forceinline__ void mma16(float c[4], const uint32_t a[4],
                                      uint32_t b0, uint32_t b1) {
    asm volatile("mma.sync.aligned.m16n8k16.row.col.f32.f16.f16.f32 "
        "{%0,%1,%2,%3}, {%4,%5,%6,%7}, {%8,%9}, {%0,%1,%2,%3};"
        : "+f"(c[0]), "+f"(c[1]), "+f"(c[2]), "+f"(c[3])
        : "r"(a[0]), "r"(a[1]), "r"(a[2]), "r"(a[3]), "r"(b0), "r"(b1));
}

__global__ void __launch_bounds__(THREADS, 7)
vq_fp16_kernel(const float* __restrict__ x, const float* __restrict__ cb,
               int tokens, int K,
               float* __restrict__ q_out, float* __restrict__ idx_out,
               float* __restrict__ loss_out)
{
    extern __shared__ uint32_t sm[];
    float*    s_w2  = (float*)(sm + OFF_W2);
    float*    s_gw  = (float*)(sm + OFF_GW);
    uint32_t* s_res = sm + OFF_RES;
    float*    s_red = (float*)(sm + OFF_RED);
    int*      s_amb = (int*)(sm + OFF_AMB);
    int*      s_misc = (int*)(sm + OFF_MISC);

    const int tid = threadIdx.x;
    const int token = blockIdx.x * TPB + tid;
    const bool tok_ok = (token < tokens);

    if (tid == 0) { s_misc[0] = 0; s_misc[2] = 0; }
    __syncthreads();

    // ---- stage B (fp16 planes), exact w2, block wmax ----
    float wmax_l = 0.f;
    #pragma unroll
    for (int s = 0; s < 4; s++) {
        const int k = tid + s * THREADS;
        float wv[D];
        if (k < K) {
            const float4* wp = (const float4*)(cb + (size_t)k * D);
            const float4 a = wp[0], b = wp[1], c = wp[2];
            wv[0]=a.x; wv[1]=a.y; wv[2]=a.z; wv[3]=a.w;
            wv[4]=b.x; wv[5]=b.y; wv[6]=b.z; wv[7]=b.w;
            wv[8]=c.x; wv[9]=c.y; wv[10]=c.z; wv[11]=c.w;
        } else {
            #pragma unroll
            for (int d = 0; d < D; d++) wv[d] = 0.f;
        }
        float w2 = 0.f;
        #pragma unroll
        for (int d = 0; d < D; d++) w2 = fmaf(wv[d], wv[d], w2);   // bit-faithful chain
        s_w2[k] = w2;
        #pragma unroll
        for (int d = 0; d < D; d++) wmax_l = fmaxf(wmax_l, fabsf(wv[d]));
        const float bias = (k < K) ? (-0.5f * w2) : -60000.f;      // sentinel never wins
        // plane 0: k-dims 0..7 ; plane 1: k-dims 8..15 (12 = bias)
        #pragma unroll
        for (int t = 0; t < 4; t++)
            sm[OFF_B + t * BSTR + k] = pack_h2(wv[2*t], wv[2*t+1]);
        sm[OFF_B + BPL + 0 * BSTR + k] = pack_h2(wv[8], wv[9]);
        sm[OFF_B + BPL + 1 * BSTR + k] = pack_h2(wv[10], wv[11]);
        sm[OFF_B + BPL + 2 * BSTR + k] = pack_h2(bias, 0.f);
        sm[OFF_B + BPL + 3 * BSTR + k] = 0;
    }
    atomicMax(&s_misc[2], __float_as_int(wmax_l));

    // ---- stage A (fp16) + sum|x| for per-token window ----
    {
        float xv[D];
        float4 a = {0,0,0,0}, b = {0,0,0,0}, c = {0,0,0,0};
        if (tok_ok) { const float4* p = (const float4*)(x + (size_t)token * D); a=p[0]; b=p[1]; c=p[2]; }
        xv[0]=a.x; xv[1]=a.y; xv[2]=a.z; xv[3]=a.w;
        xv[4]=b.x; xv[5]=b.y; xv[6]=b.z; xv[7]=b.w;
        xv[8]=c.x; xv[9]=c.y; xv[10]=c.z; xv[11]=c.w;
        float sa = 0.f;
        #pragma unroll
        for (int d = 0; d < D; d++) sa += fabsf(xv[d]);
        #pragma unroll
        for (int kk = 0; kk < 6; kk++)
            sm[OFF_A + tid * ASTR + kk] = pack_h2(xv[2*kk], xv[2*kk+1]);
        sm[OFF_A + tid * ASTR + 6] = pack_h2(1.0f, 0.f);   // k12 = 1 -> picks up bias
        sm[OFF_A + tid * ASTR + 7] = 0;
        s_gw[tid] = sa;
    }
    __syncthreads();
    {   // per-token certify window (S units): quantization + subnormal floor + accum/ref slack
        const float wmax = __int_as_float(s_misc[2]);
        s_gw[tid] = s_gw[tid] * (1.98e-3f * wmax + 7e-8f) + 3.0e-6f;
    }
    __syncthreads();

    // ---- A fragments (resident) ----
    const int lane = tid & 31, wrp = tid >> 5;
    const int gid = lane >> 2, tig = lane & 3;
    uint32_t Af[2][4];
    #pragma unroll
    for (int mt = 0; mt < 2; mt++) {
        const int row = wrp * 32 + mt * 16 + gid;
        Af[mt][0] = sm[OFF_A + row * ASTR + tig];
        Af[mt][1] = sm[OFF_A + (row + 8) * ASTR + tig];
        Af[mt][2] = sm[OFF_A + row * ASTR + tig + 4];
        Af[mt][3] = sm[OFF_A + (row + 8) * ASTR + tig + 4];
    }

    float m1[4], m2[4];
    int   i1[4];
    #pragma unroll
    for (int r = 0; r < 4; r++) { m1[r] = -3.4e38f; m2[r] = -3.4e38f; i1[r] = 0; }

    const uint32_t* sB0 = sm + OFF_B + tig * BSTR;
    const uint32_t* sB1 = sB0 + BPL;

    // ---- main screen loop: one n8 tile (8 codes) per iter, 2 MMAs ----
    #pragma unroll 4
    for (int it = 0; it < KCB / 8; it++) {
        const int col = it * 8 + gid;
        const uint32_t b0 = sB0[col];
        const uint32_t b1 = sB1[col];
        const int kb = it * 8 + 2 * tig;
        #pragma unroll
        for (int mt = 0; mt < 2; mt++) {
            float c[4] = {0.f, 0.f, 0.f, 0.f};
            mma16(c, Af[mt], b0, b1);
            #pragma unroll
            for (int e = 0; e < 4; e++) {
                const float S = c[e];
                const int r = mt * 2 + (e >> 1);
                const int kidx = kb + (e & 1);
                m2[r] = fmaxf(m2[r], fminf(S, m1[r]));
                i1[r] = (S > m1[r]) ? kidx : i1[r];
                m1[r] = fmaxf(m1[r], S);
            }
        }
    }

    // ---- merge top-2 across the 4 tig lanes per row ----
    #pragma unroll
    for (int off = 1; off <= 2; off <<= 1) {
        #pragma unroll
        for (int r = 0; r < 4; r++) {
            const float om1 = __shfl_xor_sync(0xFFFFFFFFu, m1[r], off);
            const float om2 = __shfl_xor_sync(0xFFFFFFFFu, m2[r], off);
            const int   oi1 = __shfl_xor_sync(0xFFFFFFFFu, i1[r], off);
            const float nm2 = fmaxf(fmaxf(m2[r], om2), fminf(m1[r], om1));
            const bool take = (om1 > m1[r]) || (om1 == m1[r] && oi1 < i1[r]);
            i1[r] = take ? oi1 : i1[r];
            m1[r] = fmaxf(m1[r], om1);
            m2[r] = nm2;
        }
    }
    if (tig == 0) {
        #pragma unroll
        for (int r = 0; r < 4; r++) {
            const int row = wrp * 32 + (r >> 1) * 16 + (r & 1) * 8 + gid;
            const bool amb = !((m1[r] - m2[r]) > s_gw[row]);
            s_res[row] = (uint32_t)i1[r] | (amb ? 0x80000000u : 0u);
        }
    }
    __syncthreads();

    // ---- collect ambiguous tokens ----
    if (tok_ok && (s_res[tid] >> 31)) {
        const int pos = atomicAdd(&s_misc[0], 1);
        s_amb[pos] = tid;
    }
    __syncthreads();

    // ---- warp-parallel exact fallback (bit-faithful fp32 chain) ----
    const int nA = s_misc[0];
    for (int a = wrp; a < nA; a += (THREADS / 32)) {
        const int trow = s_amb[a];
        const float* xp = x + (size_t)(blockIdx.x * TPB + trow) * D;
        float ax[D];
        #pragma unroll
        for (int d = 0; d < D; d++) ax[d] = xp[d];      // uniform -> broadcast
        float ax2 = 0.f;
        #pragma unroll
        for (int d = 0; d < D; d++) ax2 = fmaf(ax[d], ax[d], ax2);
        u64 key = ~0ull;
        #pragma unroll 2
        for (int j = 0; j < KCB / 32; j++) {
            const int k = lane + j * 32;
            if (k < K) {
                const float4* wp = (const float4*)(cb + (size_t)k * D);
                const float4 aa = wp[0], bb = wp[1], cc = wp[2];
                const float wv[D] = {aa.x,aa.y,aa.z,aa.w, bb.x,bb.y,bb.z,bb.w, cc.x,cc.y,cc.z,cc.w};
                float xw = ax[0] * wv[0];
                #pragma unroll
                for (int d = 1; d < D; d++) xw = fmaf(ax[d], wv[d], xw);
                const float u = fmaf(xw, -2.0f, ax2);   // fl(x2 - 2*xw)
                const float dist = u + s_w2[k];         // fl(u + w2)
                const u64 kk = ((u64)__float_as_uint(dist) << 32) | (uint32_t)k;
                key = (kk < key) ? kk : key;
            }
        }
        #pragma unroll
        for (int off = 16; off > 0; off >>= 1) {
            const u64 o = __shfl_xor_sync(0xFFFFFFFFu, key, off);
            key = (o < key) ? o : key;
        }
        if (lane == 0) s_res[trow] = (uint32_t)(key & 0x7FFFFFFFu);
    }
    __syncthreads();

    // ---- outputs: qst = fl(x + fl(q - x)), indices, loss ----
    const int best_i = (int)(s_res[tid] & 0x7FFFFFFFu);
    float lsum = 0.f;
    if (tok_ok) {
        const float4* xp4 = (const float4*)(x + (size_t)token * D);
        const float4 xa = xp4[0], xb = xp4[1], xc = xp4[2];
        const float xv[D] = {xa.x,xa.y,xa.z,xa.w, xb.x,xb.y,xb.z,xb.w, xc.x,xc.y,xc.z,xc.w};
        const float4* wp = (const float4*)(cb + (size_t)best_i * D);
        const float4 aa = wp[0], bb = wp[1], cc = wp[2];
        const float qv[D] = {aa.x,aa.y,aa.z,aa.w, bb.x,bb.y,bb.z,bb.w, cc.x,cc.y,cc.z,cc.w};
        float qst[D];
        #pragma unroll
        for (int d = 0; d < D; d++) {
            const float d1 = qv[d] - xv[d];
            qst[d] = xv[d] + d1;
            lsum = fmaf(d1, d1, lsum);
        }
        if (q_out) {
            float4* o = (float4*)(q_out + (size_t)token * D);
            o[0] = make_float4(qst[0], qst[1], qst[2],  qst[3]);
            o[1] = make_float4(qst[4], qst[5], qst[6],  qst[7]);
            o[2] = make_float4(qst[8], qst[9], qst[10], qst[11]);
        }
        if (idx_out) idx_out[token] = (float)best_i;
    }

    if (loss_out) {
        s_red[tid] = lsum;
        __syncthreads();
        #pragma unroll
        for (int s = THREADS / 2; s > 0; s >>= 1) {
            if (tid < s) s_red[tid] += s_red[tid + s];
            __syncthreads();
        }
        if (tid == 0) {
            g_partial[blockIdx.x] = s_red[0];
            __threadfence();
            const unsigned old = atomicInc(&g_ctr, gridDim.x - 1);   // self-resets
            s_misc[1] = (old == gridDim.x - 1);
        }
        __syncthreads();
        if (s_misc[1]) {
            __threadfence();
            float v = 0.f;
            for (int i = tid; i < (int)gridDim.x; i += THREADS) v += g_partial[i];
            s_red[tid] = v;
            __syncthreads();
            #pragma unroll
            for (int s = THREADS / 2; s > 0; s >>= 1) {
                if (tid < s) s_red[tid] += s_red[tid + s];
                __syncthreads();
            }
            if (tid == 0) {
                const float m = s_red[0] / ((float)tokens * 12.0f);
                loss_out[0] = m + 0.25f * m;
            }
        }
    }
}

extern "C" void kernel_launch(void* const* d_in, const int* in_sizes, int n_in,
                              void* d_out, int out_size)
{
    const float* x;
    const float* cb;
    int xs, cs;
    if (in_sizes[0] >= in_sizes[1]) {
        x = (const float*)d_in[0]; cb = (const float*)d_in[1];
        xs = in_sizes[0]; cs = in_sizes[1];
    } else {
        x = (const float*)d_in[1]; cb = (const float*)d_in[0];
        xs = in_sizes[1]; cs = in_sizes[0];
    }
    const int tokens = xs / D;
    int K = cs / D;
    if (K > KCB) K = KCB;

    float* out = (float*)d_out;
    const long long QN = (long long)tokens * D;

    float* q_out    = nullptr;
    float* idx_out  = nullptr;
    float* loss_out = nullptr;
    if ((long long)out_size == (long long)tokens) {
        idx_out = out;
    } else {
        q_out = out;
        if ((long long)out_size >= QN + tokens)     idx_out  = out + QN;
        if ((long long)out_size >= QN + tokens + 1) loss_out = out + QN + tokens;
        else if ((long long)out_size == QN + 1)     loss_out = out + QN;
    }

    int grid = (tokens + TPB - 1) / TPB;   // 1024 for this shape
    if (grid > 2048) grid = 2048;          // g_partial capacity (not hit)

    vq_fp16_kernel<<<grid, THREADS, SMEM_DYN>>>(x, cb, tokens, K, q_out, idx_out, loss_out);
}